// round 2
// baseline (speedup 1.0000x reference)
#include <cuda_runtime.h>
#include <math.h>

// ---------------------------------------------------------------------------
// Problem constants: B=4, T=2048, E=1024, H=16, D=64
// ---------------------------------------------------------------------------
#define B_  4
#define T_  2048
#define E_  1024
#define H_  16
#define D_  64
#define M_  (B_*T_)        // 8192 rows

// Scratch (device globals; no runtime allocation allowed)
__device__ float g_qlin[M_*E_];
__device__ float g_klin[M_*E_];
__device__ float g_vlin[M_*E_];
__device__ float g_qh[M_*E_];   // [B*H][T][D]
__device__ float g_kh[M_*E_];
__device__ float g_vh[M_*E_];
__device__ float g_olin[M_*E_]; // [B][T][E]

// ---------------------------------------------------------------------------
// SGEMM:  C[M,N] = A[M,K] @ B[N,K]^T + bias[N]
// 128x128 tile, BK=16, 256 threads, 8x8 microtile
// ---------------------------------------------------------------------------
__global__ __launch_bounds__(256) void sgemm_nt_bias(
    const float* __restrict__ A, const float* __restrict__ Bm,
    const float* __restrict__ bias, float* __restrict__ C,
    int M, int N, int K)
{
    __shared__ float As[16 * 128];
    __shared__ float Bs[16 * 128];

    const int tid = threadIdx.x;
    const int tx = tid & 15;        // n direction
    const int ty = tid >> 4;        // m direction
    const int m0 = blockIdx.y * 128;
    const int n0 = blockIdx.x * 128;

    float acc[8][8];
#pragma unroll
    for (int i = 0; i < 8; i++)
#pragma unroll
        for (int j = 0; j < 8; j++) acc[i][j] = 0.f;

    for (int kt = 0; kt < K; kt += 16) {
        // load A tile (128 x 16) and B tile (128 x 16), transposed into smem
#pragma unroll
        for (int it = 0; it < 2; it++) {
            int idx = it * 256 + tid;       // float4 index, 512 total
            int r  = idx >> 2;              // row within tile (0..127)
            int kq = idx & 3;               // which float4 along k
            float4 a = *(const float4*)(A + (size_t)(m0 + r) * K + kt + kq * 4);
            As[(kq * 4 + 0) * 128 + r] = a.x;
            As[(kq * 4 + 1) * 128 + r] = a.y;
            As[(kq * 4 + 2) * 128 + r] = a.z;
            As[(kq * 4 + 3) * 128 + r] = a.w;
            float4 b = *(const float4*)(Bm + (size_t)(n0 + r) * K + kt + kq * 4);
            Bs[(kq * 4 + 0) * 128 + r] = b.x;
            Bs[(kq * 4 + 1) * 128 + r] = b.y;
            Bs[(kq * 4 + 2) * 128 + r] = b.z;
            Bs[(kq * 4 + 3) * 128 + r] = b.w;
        }
        __syncthreads();

#pragma unroll
        for (int kk = 0; kk < 16; kk++) {
            float4 a0 = *(const float4*)&As[kk * 128 + ty * 8];
            float4 a1 = *(const float4*)&As[kk * 128 + ty * 8 + 4];
            float4 b0 = *(const float4*)&Bs[kk * 128 + tx * 8];
            float4 b1 = *(const float4*)&Bs[kk * 128 + tx * 8 + 4];
            float ar[8] = {a0.x, a0.y, a0.z, a0.w, a1.x, a1.y, a1.z, a1.w};
            float br[8] = {b0.x, b0.y, b0.z, b0.w, b1.x, b1.y, b1.z, b1.w};
#pragma unroll
            for (int i = 0; i < 8; i++)
#pragma unroll
                for (int j = 0; j < 8; j++)
                    acc[i][j] += ar[i] * br[j];
        }
        __syncthreads();
    }

    // epilogue with bias
    float bv[8];
#pragma unroll
    for (int j = 0; j < 8; j++) bv[j] = bias[n0 + tx * 8 + j];

#pragma unroll
    for (int i = 0; i < 8; i++) {
        int m = m0 + ty * 8 + i;
        float* Crow = C + (size_t)m * N + n0 + tx * 8;
        float4 c0 = make_float4(acc[i][0] + bv[0], acc[i][1] + bv[1],
                                acc[i][2] + bv[2], acc[i][3] + bv[3]);
        float4 c1 = make_float4(acc[i][4] + bv[4], acc[i][5] + bv[5],
                                acc[i][6] + bv[6], acc[i][7] + bv[7]);
        *(float4*)(Crow + 0) = c0;
        *(float4*)(Crow + 4) = c1;
    }
}

// ---------------------------------------------------------------------------
// Fused RMSNorm + RoPE + transpose [B,T,H,D] -> [B*H,T,D]
// one warp per (b,t,h); lane l owns elements l and l+32 (the RoPE pair)
// v is copied/transposed without norm/rope
// ---------------------------------------------------------------------------
__global__ __launch_bounds__(256) void normrope_kernel(
    const float* __restrict__ ql, const float* __restrict__ kl,
    const float* __restrict__ vl,
    const float* __restrict__ cosp, const float* __restrict__ sinp,
    float* __restrict__ qh, float* __restrict__ kh, float* __restrict__ vh)
{
    int w    = blockIdx.x * 8 + (threadIdx.x >> 5);   // 0 .. B*T*H-1
    int lane = threadIdx.x & 31;
    int h = w & 15;
    int t = (w >> 4) & 2047;
    int b = w >> 15;

    size_t in_base  = ((size_t)(b * T_ + t)) * E_ + h * D_;
    size_t out_base = ((size_t)((b * H_ + h) * T_ + t)) * D_;

    float c = cosp[t * 32 + lane];
    float s = sinp[t * 32 + lane];

    // q: rmsnorm + rope
    {
        float x1 = ql[in_base + lane];
        float x2 = ql[in_base + lane + 32];
        float ss = x1 * x1 + x2 * x2;
#pragma unroll
        for (int o = 16; o > 0; o >>= 1) ss += __shfl_xor_sync(0xffffffffu, ss, o);
        float r = rsqrtf(ss * (1.0f / 64.0f) + 1e-6f);
        qh[out_base + lane]      = (x1 * c - x2 * s) * r;
        qh[out_base + lane + 32] = (x2 * c + x1 * s) * r;
    }
    // k: rmsnorm + rope
    {
        float x1 = kl[in_base + lane];
        float x2 = kl[in_base + lane + 32];
        float ss = x1 * x1 + x2 * x2;
#pragma unroll
        for (int o = 16; o > 0; o >>= 1) ss += __shfl_xor_sync(0xffffffffu, ss, o);
        float r = rsqrtf(ss * (1.0f / 64.0f) + 1e-6f);
        kh[out_base + lane]      = (x1 * c - x2 * s) * r;
        kh[out_base + lane + 32] = (x2 * c + x1 * s) * r;
    }
    // v: transpose only
    vh[out_base + lane]      = vl[in_base + lane];
    vh[out_base + lane + 32] = vl[in_base + lane + 32];
}

// ---------------------------------------------------------------------------
// Flash attention, causal. One q-row per thread (128 rows/block).
// K/V tiles 64x64 in SMEM, warp-broadcast float4 reads.
// Output written directly in [B,T,E] layout for the final projection.
// ---------------------------------------------------------------------------
__global__ __launch_bounds__(128) void flash_kernel(
    const float* __restrict__ Q, const float* __restrict__ Kx,
    const float* __restrict__ Vx, float* __restrict__ O)
{
    __shared__ float Ks[64 * 64];
    __shared__ float Vs[64 * 64];

    const int bh  = blockIdx.y;
    const int qt  = (int)gridDim.x - 1 - (int)blockIdx.x;  // heavy tiles first
    const int tid = threadIdx.x;
    const int row = qt * 128 + tid;                        // global q position

    const float* Qb = Q + ((size_t)bh * T_ + row) * D_;
    float q[64];
#pragma unroll
    for (int i = 0; i < 16; i++) {
        float4 v4 = *(const float4*)(Qb + i * 4);
        q[i * 4 + 0] = v4.x; q[i * 4 + 1] = v4.y;
        q[i * 4 + 2] = v4.z; q[i * 4 + 3] = v4.w;
    }

    float acc[64];
#pragma unroll
    for (int i = 0; i < 64; i++) acc[i] = 0.f;
    float mrow = -INFINITY;
    float lrow = 0.f;
    const float scale = 0.125f;   // 1/sqrt(64)

    const int nkt = 2 * qt + 2;   // causal k-tile count

#pragma unroll 1
    for (int kt = 0; kt < nkt; kt++) {
        const float4* Kb = (const float4*)(Kx + ((size_t)bh * T_ + kt * 64) * D_);
        const float4* Vb = (const float4*)(Vx + ((size_t)bh * T_ + kt * 64) * D_);
#pragma unroll
        for (int i = 0; i < 8; i++) {
            int idx = i * 128 + tid;
            ((float4*)Ks)[idx] = Kb[idx];
            ((float4*)Vs)[idx] = Vb[idx];
        }
        __syncthreads();

#pragma unroll 1
        for (int c = 0; c < 4; c++) {
            int j0 = kt * 64 + c * 16;
            if (j0 <= row) {
                float s[16];
#pragma unroll
                for (int jj = 0; jj < 16; jj++) {
                    const float4* kr = (const float4*)&Ks[(c * 16 + jj) * 64];
                    float d0 = 0.f, d1 = 0.f, d2 = 0.f, d3 = 0.f;
#pragma unroll
                    for (int dd = 0; dd < 16; dd++) {
                        float4 kv = kr[dd];
                        d0 += q[dd * 4 + 0] * kv.x;
                        d1 += q[dd * 4 + 1] * kv.y;
                        d2 += q[dd * 4 + 2] * kv.z;
                        d3 += q[dd * 4 + 3] * kv.w;
                    }
                    float sv = ((d0 + d1) + (d2 + d3)) * scale;
                    if (j0 + jj > row) sv = -INFINITY;
                    s[jj] = sv;
                }
                float cm = s[0];
#pragma unroll
                for (int jj = 1; jj < 16; jj++) cm = fmaxf(cm, s[jj]);
                float mnew = fmaxf(mrow, cm);
                float f = __expf(mrow - mnew);
                mrow = mnew;
                lrow *= f;
#pragma unroll
                for (int dd = 0; dd < 64; dd++) acc[dd] *= f;
#pragma unroll
                for (int jj = 0; jj < 16; jj++) {
                    float p = __expf(s[jj] - mnew);
                    lrow += p;
                    const float4* vr = (const float4*)&Vs[(c * 16 + jj) * 64];
#pragma unroll
                    for (int dd = 0; dd < 16; dd++) {
                        float4 vv = vr[dd];
                        acc[dd * 4 + 0] += p * vv.x;
                        acc[dd * 4 + 1] += p * vv.y;
                        acc[dd * 4 + 2] += p * vv.z;
                        acc[dd * 4 + 3] += p * vv.w;
                    }
                }
            }
        }
        __syncthreads();
    }

    float inv = 1.0f / lrow;
    int b = bh >> 4, h = bh & 15;
    float* Ob = O + ((size_t)(b * T_ + row)) * E_ + h * D_;
#pragma unroll
    for (int i = 0; i < 16; i++) {
        float4 o4 = make_float4(acc[i * 4 + 0] * inv, acc[i * 4 + 1] * inv,
                                acc[i * 4 + 2] * inv, acc[i * 4 + 3] * inv);
        *(float4*)(Ob + i * 4) = o4;
    }
}

// ---------------------------------------------------------------------------
// Launch
// ---------------------------------------------------------------------------
extern "C" void kernel_launch(void* const* d_in, const int* in_sizes, int n_in,
                              void* d_out, int out_size)
{
    const float* query = (const float*)d_in[0];
    const float* key   = (const float*)d_in[1];
    const float* value = (const float*)d_in[2];
    // d_in[3] = attn_mask (causal, implicit in kernel)
    const float* cosp  = (const float*)d_in[4];
    const float* sinp  = (const float*)d_in[5];
    const float* Wq = (const float*)d_in[6];
    const float* bq = (const float*)d_in[7];
    const float* Wk = (const float*)d_in[8];
    const float* bk = (const float*)d_in[9];
    const float* Wv = (const float*)d_in[10];
    const float* bv = (const float*)d_in[11];
    const float* Wo = (const float*)d_in[12];
    const float* bo = (const float*)d_in[13];
    float* out = (float*)d_out;

    float *qlin, *klin, *vlin, *qh, *kh, *vh, *olin;
    cudaGetSymbolAddress((void**)&qlin, g_qlin);
    cudaGetSymbolAddress((void**)&klin, g_klin);
    cudaGetSymbolAddress((void**)&vlin, g_vlin);
    cudaGetSymbolAddress((void**)&qh,   g_qh);
    cudaGetSymbolAddress((void**)&kh,   g_kh);
    cudaGetSymbolAddress((void**)&vh,   g_vh);
    cudaGetSymbolAddress((void**)&olin, g_olin);

    dim3 gemm_grid(E_ / 128, M_ / 128);   // (8, 64)

    sgemm_nt_bias<<<gemm_grid, 256>>>(query, Wq, bq, qlin, M_, E_, E_);
    sgemm_nt_bias<<<gemm_grid, 256>>>(key,   Wk, bk, klin, M_, E_, E_);
    sgemm_nt_bias<<<gemm_grid, 256>>>(value, Wv, bv, vlin, M_, E_, E_);

    normrope_kernel<<<(B_ * T_ * H_) / 8, 256>>>(qlin, klin, vlin, cosp, sinp,
                                                 qh, kh, vh);

    flash_kernel<<<dim3(T_ / 128, B_ * H_), 128>>>(qh, kh, vh, olin);

    sgemm_nt_bias<<<gemm_grid, 256>>>(olin, Wo, bo, out, M_, E_, E_);
}

// round 12
// speedup vs baseline: 1.4906x; 1.4906x over previous
#include <cuda_runtime.h>
#include <cuda_bf16.h>
#include <cstdint>
#include <math.h>

// ---------------------------------------------------------------------------
// Problem constants: B=4, T=2048, E=1024, H=16, D=64
// ---------------------------------------------------------------------------
#define B_  4
#define T_  2048
#define E_  1024
#define H_  16
#define D_  64
#define M_  (B_*T_)        // 8192 rows

// Scratch (device globals; no runtime allocation allowed)
__device__ float g_qlin[M_*E_];
__device__ float g_klin[M_*E_];
__device__ float g_vlin[M_*E_];
__device__ float g_qh[M_*E_];   // [B*H][T][D]
__device__ float g_kh[M_*E_];
__device__ float g_vh[M_*E_];
__device__ float g_olin[M_*E_]; // [B][T][E]
__device__ __nv_bfloat16 g_ahi[M_*E_];
__device__ __nv_bfloat16 g_alo[M_*E_];
__device__ __nv_bfloat16 g_whi[E_*E_];
__device__ __nv_bfloat16 g_wlo[E_*E_];

// ---------------------------------------------------------------------------
// PTX helpers (sm_80-class: portable on sm_103 without the 'a' suffix)
// ---------------------------------------------------------------------------
__device__ __forceinline__ uint32_t smem_u32(const void* p) {
    uint32_t a;
    asm("{ .reg .u64 t; cvta.to.shared.u64 t, %1; cvt.u32.u64 %0, t; }"
        : "=r"(a) : "l"(p));
    return a;
}
__device__ __forceinline__ void cp_async16(uint32_t dst, const void* src) {
    asm volatile("cp.async.cg.shared.global [%0], [%1], 16;"
                 :: "r"(dst), "l"(src));
}
#define CP_COMMIT() asm volatile("cp.async.commit_group;" ::: "memory")
#define CP_WAIT(n)  asm volatile("cp.async.wait_group %0;" :: "n"(n) : "memory")

__device__ __forceinline__ void ldsm4(uint32_t* r, uint32_t addr) {
    asm volatile("ldmatrix.sync.aligned.m8n8.x4.shared.b16 {%0,%1,%2,%3}, [%4];"
                 : "=r"(r[0]), "=r"(r[1]), "=r"(r[2]), "=r"(r[3]) : "r"(addr));
}
__device__ __forceinline__ void mma16816(float* d, const uint32_t* a,
                                         const uint32_t* b) {
    asm volatile(
        "mma.sync.aligned.m16n8k16.row.col.f32.bf16.bf16.f32 "
        "{%0,%1,%2,%3}, {%4,%5,%6,%7}, {%8,%9}, {%0,%1,%2,%3};"
        : "+f"(d[0]), "+f"(d[1]), "+f"(d[2]), "+f"(d[3])
        : "r"(a[0]), "r"(a[1]), "r"(a[2]), "r"(a[3]), "r"(b[0]), "r"(b[1]));
}

// ---------------------------------------------------------------------------
// fp32 -> bf16 hi/lo split
// ---------------------------------------------------------------------------
__global__ __launch_bounds__(256) void cvt_split(
    const float* __restrict__ x, __nv_bfloat16* __restrict__ hi,
    __nv_bfloat16* __restrict__ lo, int n)
{
    int i = (blockIdx.x * 256 + threadIdx.x) * 4;
    if (i >= n) return;
    float4 v = *(const float4*)(x + i);
    float a[4] = {v.x, v.y, v.z, v.w};
    __nv_bfloat16 h[4], l[4];
#pragma unroll
    for (int j = 0; j < 4; j++) {
        h[j] = __float2bfloat16(a[j]);
        l[j] = __float2bfloat16(a[j] - __bfloat162float(h[j]));
    }
    uint16_t* hp = (uint16_t*)h;
    uint16_t* lp = (uint16_t*)l;
    uint2 hv = make_uint2((uint32_t)hp[0] | ((uint32_t)hp[1] << 16),
                          (uint32_t)hp[2] | ((uint32_t)hp[3] << 16));
    uint2 lv = make_uint2((uint32_t)lp[0] | ((uint32_t)lp[1] << 16),
                          (uint32_t)lp[2] | ((uint32_t)lp[3] << 16));
    *(uint2*)(hi + i) = hv;
    *(uint2*)(lo + i) = lv;
}

// ---------------------------------------------------------------------------
// bf16-split GEMM on mma.sync:  C[M,N] = A[M,K] @ W[N,K]^T + bias
// C = Ahi@Whi + Ahi@Wlo + Alo@Whi (fp32 accum)
// CTA tile 128x128, BK=32, 8 warps (2x4), warp tile 64x32.
// SMEM: 4 tiles (Ahi,Alo,Whi,Wlo) of 128 rows x 32 bf16, row stride 80B
// (conflict-free for ldmatrix), double buffered: 2*4*10240 = 81920 B.
// ---------------------------------------------------------------------------
#define GT_STRIDE 80                 // bytes per smem tile row
#define GT_BYTES  (128 * GT_STRIDE)  // 10240 per tile
#define GBUF_BYTES (4 * GT_BYTES)    // 40960 per buffer
#define GSMEM_TOTAL (2 * GBUF_BYTES) // 81920

__global__ __launch_bounds__(256) void gemm_mma(
    const __nv_bfloat16* __restrict__ Ahi, const __nv_bfloat16* __restrict__ Alo,
    const __nv_bfloat16* __restrict__ Whi, const __nv_bfloat16* __restrict__ Wlo,
    const float* __restrict__ bias, float* __restrict__ C)
{
    extern __shared__ char smem[];
    const int tid  = threadIdx.x;
    const int lane = tid & 31;
    const int wid  = tid >> 5;
    const int wm   = wid & 1;        // 0..1 (m)
    const int wn   = wid >> 1;       // 0..3 (n)
    const int m0 = blockIdx.y * 128, n0 = blockIdx.x * 128;
    const uint32_t sb = smem_u32(smem);

    const char* pA[2] = { (const char*)(Ahi + (size_t)m0 * E_),
                          (const char*)(Alo + (size_t)m0 * E_) };
    const char* pW[2] = { (const char*)(Whi + (size_t)n0 * E_),
                          (const char*)(Wlo + (size_t)n0 * E_) };

    float acc[4][4][4];
#pragma unroll
    for (int i = 0; i < 4; i++)
#pragma unroll
        for (int j = 0; j < 4; j++)
#pragma unroll
            for (int k = 0; k < 4; k++) acc[i][j][k] = 0.f;

    // ---- async tile loader: one chunk = 4 tiles of 128x32 bf16 ----
    auto load_chunk = [&](int chunk, int buf) {
#pragma unroll
        for (int p = 0; p < 8; p++) {
            int idx  = p * 256 + tid;          // 0..2047
            int tile = idx >> 9;               // 0..3
            int r    = (idx >> 2) & 127;
            int c    = idx & 3;
            const char* base = (tile == 0) ? pA[0] :
                               (tile == 1) ? pA[1] :
                               (tile == 2) ? pW[0] : pW[1];
            const char* src = base + (size_t)r * 2048 + chunk * 64 + c * 16;
            uint32_t dst = sb + buf * GBUF_BYTES + tile * GT_BYTES
                         + r * GT_STRIDE + c * 16;
            cp_async16(dst, src);
        }
    };

    // ldmatrix address builders (lane-dependent)
    auto addrA = [&](uint32_t tbase, int mt, int ks) -> uint32_t {
        int row = wm * 64 + mt * 16 + (lane & 15);
        int kh  = (lane >> 4) & 1;
        return tbase + row * GT_STRIDE + ks * 32 + kh * 16;
    };
    auto addrB = [&](uint32_t tbase, int np, int ks) -> uint32_t {
        int row = wn * 32 + np * 16 + (lane & 7) + (((lane >> 4) & 1) << 3);
        int kh  = (lane >> 3) & 1;
        return tbase + row * GT_STRIDE + ks * 32 + kh * 16;
    };

    load_chunk(0, 0);
    CP_COMMIT();

    const int NCHUNK = E_ / 32;   // 32
#pragma unroll 1
    for (int ch = 0; ch < NCHUNK; ch++) {
        const int buf = ch & 1;
        if (ch + 1 < NCHUNK) {
            load_chunk(ch + 1, buf ^ 1);
            CP_COMMIT();
            CP_WAIT(1);
        } else {
            CP_WAIT(0);
        }
        __syncthreads();

        const uint32_t tAhi = sb + buf * GBUF_BYTES;
        const uint32_t tAlo = tAhi + GT_BYTES;
        const uint32_t tWhi = tAhi + 2 * GT_BYTES;
        const uint32_t tWlo = tAhi + 3 * GT_BYTES;

#pragma unroll
        for (int ks = 0; ks < 2; ks++) {
            uint32_t ahi[4][4], alo[4][4], bhi[2][4], blo[2][4];
#pragma unroll
            for (int mt = 0; mt < 4; mt++) ldsm4(ahi[mt], addrA(tAhi, mt, ks));
#pragma unroll
            for (int mt = 0; mt < 4; mt++) ldsm4(alo[mt], addrA(tAlo, mt, ks));
#pragma unroll
            for (int np = 0; np < 2; np++) ldsm4(bhi[np], addrB(tWhi, np, ks));
#pragma unroll
            for (int np = 0; np < 2; np++) ldsm4(blo[np], addrB(tWlo, np, ks));
#pragma unroll
            for (int mt = 0; mt < 4; mt++)
#pragma unroll
                for (int nt = 0; nt < 4; nt++) {
                    const int np = nt >> 1, hf = (nt & 1) * 2;
                    mma16816(acc[mt][nt], ahi[mt], &bhi[np][hf]);   // hi*hi
                    mma16816(acc[mt][nt], ahi[mt], &blo[np][hf]);   // hi*lo
                    mma16816(acc[mt][nt], alo[mt], &bhi[np][hf]);   // lo*hi
                }
        }
        __syncthreads();
    }

    // ---- epilogue: bias + store ----
    const int quad = lane >> 2, qd = (lane & 3) * 2;
#pragma unroll
    for (int mt = 0; mt < 4; mt++) {
#pragma unroll
        for (int nt = 0; nt < 4; nt++) {
            int row0 = m0 + wm * 64 + mt * 16 + quad;
            int col  = n0 + wn * 32 + nt * 8 + qd;
            float b0 = bias[col], b1 = bias[col + 1];
            float2 v0 = make_float2(acc[mt][nt][0] + b0, acc[mt][nt][1] + b1);
            float2 v1 = make_float2(acc[mt][nt][2] + b0, acc[mt][nt][3] + b1);
            *(float2*)(C + (size_t)row0 * E_ + col) = v0;
            *(float2*)(C + (size_t)(row0 + 8) * E_ + col) = v1;
        }
    }
}

// ---------------------------------------------------------------------------
// Fused RMSNorm + RoPE + transpose [B,T,H,D] -> [B*H,T,D]
// ---------------------------------------------------------------------------
__global__ __launch_bounds__(256) void normrope_kernel(
    const float* __restrict__ ql, const float* __restrict__ kl,
    const float* __restrict__ vl,
    const float* __restrict__ cosp, const float* __restrict__ sinp,
    float* __restrict__ qh, float* __restrict__ kh, float* __restrict__ vh)
{
    int w    = blockIdx.x * 8 + (threadIdx.x >> 5);
    int lane = threadIdx.x & 31;
    int h = w & 15;
    int t = (w >> 4) & 2047;
    int b = w >> 15;

    size_t in_base  = ((size_t)(b * T_ + t)) * E_ + h * D_;
    size_t out_base = ((size_t)((b * H_ + h) * T_ + t)) * D_;

    float c = cosp[t * 32 + lane];
    float s = sinp[t * 32 + lane];

    {
        float x1 = ql[in_base + lane];
        float x2 = ql[in_base + lane + 32];
        float ss = x1 * x1 + x2 * x2;
#pragma unroll
        for (int o = 16; o > 0; o >>= 1) ss += __shfl_xor_sync(0xffffffffu, ss, o);
        float r = rsqrtf(ss * (1.0f / 64.0f) + 1e-6f);
        qh[out_base + lane]      = (x1 * c - x2 * s) * r;
        qh[out_base + lane + 32] = (x2 * c + x1 * s) * r;
    }
    {
        float x1 = kl[in_base + lane];
        float x2 = kl[in_base + lane + 32];
        float ss = x1 * x1 + x2 * x2;
#pragma unroll
        for (int o = 16; o > 0; o >>= 1) ss += __shfl_xor_sync(0xffffffffu, ss, o);
        float r = rsqrtf(ss * (1.0f / 64.0f) + 1e-6f);
        kh[out_base + lane]      = (x1 * c - x2 * s) * r;
        kh[out_base + lane + 32] = (x2 * c + x1 * s) * r;
    }
    vh[out_base + lane]      = vl[in_base + lane];
    vh[out_base + lane + 32] = vl[in_base + lane + 32];
}

// ---------------------------------------------------------------------------
// Flash attention, causal. One q-row per thread (128 rows/block). fp32.
// ---------------------------------------------------------------------------
__global__ __launch_bounds__(128) void flash_kernel(
    const float* __restrict__ Q, const float* __restrict__ Kx,
    const float* __restrict__ Vx, float* __restrict__ O)
{
    __shared__ float Ks[64 * 64];
    __shared__ float Vs[64 * 64];

    const int bh  = blockIdx.y;
    const int qt  = (int)gridDim.x - 1 - (int)blockIdx.x;
    const int tid = threadIdx.x;
    const int row = qt * 128 + tid;

    const float* Qb = Q + ((size_t)bh * T_ + row) * D_;
    float q[64];
#pragma unroll
    for (int i = 0; i < 16; i++) {
        float4 v4 = *(const float4*)(Qb + i * 4);
        q[i * 4 + 0] = v4.x; q[i * 4 + 1] = v4.y;
        q[i * 4 + 2] = v4.z; q[i * 4 + 3] = v4.w;
    }

    float acc[64];
#pragma unroll
    for (int i = 0; i < 64; i++) acc[i] = 0.f;
    float mrow = -INFINITY;
    float lrow = 0.f;
    const float scale = 0.125f;

    const int nkt = 2 * qt + 2;

#pragma unroll 1
    for (int kt = 0; kt < nkt; kt++) {
        const float4* Kb = (const float4*)(Kx + ((size_t)bh * T_ + kt * 64) * D_);
        const float4* Vb = (const float4*)(Vx + ((size_t)bh * T_ + kt * 64) * D_);
#pragma unroll
        for (int i = 0; i < 8; i++) {
            int idx = i * 128 + tid;
            ((float4*)Ks)[idx] = Kb[idx];
            ((float4*)Vs)[idx] = Vb[idx];
        }
        __syncthreads();

#pragma unroll 1
        for (int c = 0; c < 4; c++) {
            int j0 = kt * 64 + c * 16;
            if (j0 <= row) {
                float s[16];
#pragma unroll
                for (int jj = 0; jj < 16; jj++) {
                    const float4* kr = (const float4*)&Ks[(c * 16 + jj) * 64];
                    float d0 = 0.f, d1 = 0.f, d2 = 0.f, d3 = 0.f;
#pragma unroll
                    for (int dd = 0; dd < 16; dd++) {
                        float4 kv = kr[dd];
                        d0 += q[dd * 4 + 0] * kv.x;
                        d1 += q[dd * 4 + 1] * kv.y;
                        d2 += q[dd * 4 + 2] * kv.z;
                        d3 += q[dd * 4 + 3] * kv.w;
                    }
                    float sv = ((d0 + d1) + (d2 + d3)) * scale;
                    if (j0 + jj > row) sv = -INFINITY;
                    s[jj] = sv;
                }
                float cm = s[0];
#pragma unroll
                for (int jj = 1; jj < 16; jj++) cm = fmaxf(cm, s[jj]);
                float mnew = fmaxf(mrow, cm);
                float f = __expf(mrow - mnew);
                mrow = mnew;
                lrow *= f;
#pragma unroll
                for (int dd = 0; dd < 64; dd++) acc[dd] *= f;
#pragma unroll
                for (int jj = 0; jj < 16; jj++) {
                    float p = __expf(s[jj] - mnew);
                    lrow += p;
                    const float4* vr = (const float4*)&Vs[(c * 16 + jj) * 64];
#pragma unroll
                    for (int dd = 0; dd < 16; dd++) {
                        float4 vv = vr[dd];
                        acc[dd * 4 + 0] += p * vv.x;
                        acc[dd * 4 + 1] += p * vv.y;
                        acc[dd * 4 + 2] += p * vv.z;
                        acc[dd * 4 + 3] += p * vv.w;
                    }
                }
            }
        }
        __syncthreads();
    }

    float inv = 1.0f / lrow;
    int b = bh >> 4, h = bh & 15;
    float* Ob = O + ((size_t)(b * T_ + row)) * E_ + h * D_;
#pragma unroll
    for (int i = 0; i < 16; i++) {
        float4 o4 = make_float4(acc[i * 4 + 0] * inv, acc[i * 4 + 1] * inv,
                                acc[i * 4 + 2] * inv, acc[i * 4 + 3] * inv);
        *(float4*)(Ob + i * 4) = o4;
    }
}

// ---------------------------------------------------------------------------
// Launch
// ---------------------------------------------------------------------------
extern "C" void kernel_launch(void* const* d_in, const int* in_sizes, int n_in,
                              void* d_out, int out_size)
{
    const float* query = (const float*)d_in[0];
    const float* key   = (const float*)d_in[1];
    const float* value = (const float*)d_in[2];
    const float* cosp  = (const float*)d_in[4];
    const float* sinp  = (const float*)d_in[5];
    const float* Wq = (const float*)d_in[6];
    const float* bq = (const float*)d_in[7];
    const float* Wk = (const float*)d_in[8];
    const float* bk = (const float*)d_in[9];
    const float* Wv = (const float*)d_in[10];
    const float* bv = (const float*)d_in[11];
    const float* Wo = (const float*)d_in[12];
    const float* bo = (const float*)d_in[13];
    float* out = (float*)d_out;

    float *qlin, *klin, *vlin, *qh, *kh, *vh, *olin;
    __nv_bfloat16 *ahi, *alo, *whi, *wlo;
    cudaGetSymbolAddress((void**)&qlin, g_qlin);
    cudaGetSymbolAddress((void**)&klin, g_klin);
    cudaGetSymbolAddress((void**)&vlin, g_vlin);
    cudaGetSymbolAddress((void**)&qh,   g_qh);
    cudaGetSymbolAddress((void**)&kh,   g_kh);
    cudaGetSymbolAddress((void**)&vh,   g_vh);
    cudaGetSymbolAddress((void**)&olin, g_olin);
    cudaGetSymbolAddress((void**)&ahi,  g_ahi);
    cudaGetSymbolAddress((void**)&alo,  g_alo);
    cudaGetSymbolAddress((void**)&whi,  g_whi);
    cudaGetSymbolAddress((void**)&wlo,  g_wlo);

    cudaFuncSetAttribute(gemm_mma, cudaFuncAttributeMaxDynamicSharedMemorySize,
                         GSMEM_TOTAL);

    const int nA = M_ * E_, nW = E_ * E_;
    dim3 ggrid(E_ / 128, M_ / 128);   // (8, 64)

    // Q projection
    cvt_split<<<nA / 1024, 256>>>(query, ahi, alo, nA);
    cvt_split<<<nW / 1024, 256>>>(Wq, whi, wlo, nW);
    gemm_mma<<<ggrid, 256, GSMEM_TOTAL>>>(ahi, alo, whi, wlo, bq, qlin);
    // K projection
    cvt_split<<<nA / 1024, 256>>>(key, ahi, alo, nA);
    cvt_split<<<nW / 1024, 256>>>(Wk, whi, wlo, nW);
    gemm_mma<<<ggrid, 256, GSMEM_TOTAL>>>(ahi, alo, whi, wlo, bk, klin);
    // V projection
    cvt_split<<<nA / 1024, 256>>>(value, ahi, alo, nA);
    cvt_split<<<nW / 1024, 256>>>(Wv, whi, wlo, nW);
    gemm_mma<<<ggrid, 256, GSMEM_TOTAL>>>(ahi, alo, whi, wlo, bv, vlin);

    normrope_kernel<<<(B_ * T_ * H_) / 8, 256>>>(qlin, klin, vlin, cosp, sinp,
                                                 qh, kh, vh);

    flash_kernel<<<dim3(T_ / 128, B_ * H_), 128>>>(qh, kh, vh, olin);

    // Output projection
    cvt_split<<<nA / 1024, 256>>>(olin, ahi, alo, nA);
    cvt_split<<<nW / 1024, 256>>>(Wo, whi, wlo, nW);
    gemm_mma<<<ggrid, 256, GSMEM_TOTAL>>>(ahi, alo, whi, wlo, bo, out);
}

// round 13
// speedup vs baseline: 3.1151x; 2.0899x over previous
#include <cuda_runtime.h>
#include <cuda_bf16.h>
#include <cstdint>
#include <math.h>

// ---------------------------------------------------------------------------
// Problem constants: B=4, T=2048, E=1024, H=16, D=64
// ---------------------------------------------------------------------------
#define B_  4
#define T_  2048
#define E_  1024
#define H_  16
#define D_  64
#define M_  (B_*T_)        // 8192 rows

// Scratch (device globals; no runtime allocation allowed)
__device__ float g_qlin[M_*E_];
__device__ float g_klin[M_*E_];
__device__ float g_vlin[M_*E_];
__device__ __nv_bfloat16 g_ahi[M_*E_];
__device__ __nv_bfloat16 g_alo[M_*E_];
__device__ __nv_bfloat16 g_whi[E_*E_];
__device__ __nv_bfloat16 g_wlo[E_*E_];
// bf16 hi/lo q,k,v in [B*H][T][D] layout for MMA flash
__device__ __nv_bfloat16 g_qhi[M_*E_];
__device__ __nv_bfloat16 g_qlo[M_*E_];
__device__ __nv_bfloat16 g_khi[M_*E_];
__device__ __nv_bfloat16 g_klo[M_*E_];
__device__ __nv_bfloat16 g_vhi[M_*E_];
__device__ __nv_bfloat16 g_vlo[M_*E_];

// ---------------------------------------------------------------------------
// PTX helpers (sm_80-class: portable on sm_103 without the 'a' suffix)
// ---------------------------------------------------------------------------
__device__ __forceinline__ uint32_t smem_u32(const void* p) {
    uint32_t a;
    asm("{ .reg .u64 t; cvta.to.shared.u64 t, %1; cvt.u32.u64 %0, t; }"
        : "=r"(a) : "l"(p));
    return a;
}
__device__ __forceinline__ void cp_async16(uint32_t dst, const void* src) {
    asm volatile("cp.async.cg.shared.global [%0], [%1], 16;"
                 :: "r"(dst), "l"(src));
}
#define CP_COMMIT() asm volatile("cp.async.commit_group;" ::: "memory")
#define CP_WAIT(n)  asm volatile("cp.async.wait_group %0;" :: "n"(n) : "memory")

__device__ __forceinline__ void ldsm4(uint32_t* r, uint32_t addr) {
    asm volatile("ldmatrix.sync.aligned.m8n8.x4.shared.b16 {%0,%1,%2,%3}, [%4];"
                 : "=r"(r[0]), "=r"(r[1]), "=r"(r[2]), "=r"(r[3]) : "r"(addr));
}
__device__ __forceinline__ void ldsm4t(uint32_t* r, uint32_t addr) {
    asm volatile("ldmatrix.sync.aligned.m8n8.x4.trans.shared.b16 {%0,%1,%2,%3}, [%4];"
                 : "=r"(r[0]), "=r"(r[1]), "=r"(r[2]), "=r"(r[3]) : "r"(addr));
}
__device__ __forceinline__ void mma16816(float* d, const uint32_t* a,
                                         const uint32_t* b) {
    asm volatile(
        "mma.sync.aligned.m16n8k16.row.col.f32.bf16.bf16.f32 "
        "{%0,%1,%2,%3}, {%4,%5,%6,%7}, {%8,%9}, {%0,%1,%2,%3};"
        : "+f"(d[0]), "+f"(d[1]), "+f"(d[2]), "+f"(d[3])
        : "r"(a[0]), "r"(a[1]), "r"(a[2]), "r"(a[3]), "r"(b[0]), "r"(b[1]));
}
// pack two floats into bf16x2 (lo in low half)
__device__ __forceinline__ uint32_t packbf(float lo, float hi) {
    uint32_t r;
    asm("cvt.rn.bf16x2.f32 %0, %1, %2;" : "=r"(r) : "f"(hi), "f"(lo));
    return r;
}
__device__ __forceinline__ void split_pack(float p0, float p1,
                                           uint32_t& hi, uint32_t& lo) {
    hi = packbf(p0, p1);
    __nv_bfloat162 h = *reinterpret_cast<__nv_bfloat162*>(&hi);
    float2 hf = __bfloat1622float2(h);
    lo = packbf(p0 - hf.x, p1 - hf.y);
}

// ---------------------------------------------------------------------------
// fp32 -> bf16 hi/lo split
// ---------------------------------------------------------------------------
__global__ __launch_bounds__(256) void cvt_split(
    const float* __restrict__ x, __nv_bfloat16* __restrict__ hi,
    __nv_bfloat16* __restrict__ lo, int n)
{
    int i = (blockIdx.x * 256 + threadIdx.x) * 4;
    if (i >= n) return;
    float4 v = *(const float4*)(x + i);
    float a[4] = {v.x, v.y, v.z, v.w};
    __nv_bfloat16 h[4], l[4];
#pragma unroll
    for (int j = 0; j < 4; j++) {
        h[j] = __float2bfloat16(a[j]);
        l[j] = __float2bfloat16(a[j] - __bfloat162float(h[j]));
    }
    uint16_t* hp = (uint16_t*)h;
    uint16_t* lp = (uint16_t*)l;
    uint2 hv = make_uint2((uint32_t)hp[0] | ((uint32_t)hp[1] << 16),
                          (uint32_t)hp[2] | ((uint32_t)hp[3] << 16));
    uint2 lv = make_uint2((uint32_t)lp[0] | ((uint32_t)lp[1] << 16),
                          (uint32_t)lp[2] | ((uint32_t)lp[3] << 16));
    *(uint2*)(hi + i) = hv;
    *(uint2*)(lo + i) = lv;
}

// ---------------------------------------------------------------------------
// bf16-split GEMM on mma.sync:  C[M,N] = A[M,K] @ W[N,K]^T + bias
// ---------------------------------------------------------------------------
#define GT_STRIDE 80
#define GT_BYTES  (128 * GT_STRIDE)
#define GBUF_BYTES (4 * GT_BYTES)
#define GSMEM_TOTAL (2 * GBUF_BYTES)

__global__ __launch_bounds__(256) void gemm_mma(
    const __nv_bfloat16* __restrict__ Ahi, const __nv_bfloat16* __restrict__ Alo,
    const __nv_bfloat16* __restrict__ Whi, const __nv_bfloat16* __restrict__ Wlo,
    const float* __restrict__ bias, float* __restrict__ C)
{
    extern __shared__ char smem[];
    const int tid  = threadIdx.x;
    const int lane = tid & 31;
    const int wid  = tid >> 5;
    const int wm   = wid & 1;
    const int wn   = wid >> 1;
    const int m0 = blockIdx.y * 128, n0 = blockIdx.x * 128;
    const uint32_t sb = smem_u32(smem);

    const char* pA[2] = { (const char*)(Ahi + (size_t)m0 * E_),
                          (const char*)(Alo + (size_t)m0 * E_) };
    const char* pW[2] = { (const char*)(Whi + (size_t)n0 * E_),
                          (const char*)(Wlo + (size_t)n0 * E_) };

    float acc[4][4][4];
#pragma unroll
    for (int i = 0; i < 4; i++)
#pragma unroll
        for (int j = 0; j < 4; j++)
#pragma unroll
            for (int k = 0; k < 4; k++) acc[i][j][k] = 0.f;

    auto load_chunk = [&](int chunk, int buf) {
#pragma unroll
        for (int p = 0; p < 8; p++) {
            int idx  = p * 256 + tid;
            int tile = idx >> 9;
            int r    = (idx >> 2) & 127;
            int c    = idx & 3;
            const char* base = (tile == 0) ? pA[0] :
                               (tile == 1) ? pA[1] :
                               (tile == 2) ? pW[0] : pW[1];
            const char* src = base + (size_t)r * 2048 + chunk * 64 + c * 16;
            uint32_t dst = sb + buf * GBUF_BYTES + tile * GT_BYTES
                         + r * GT_STRIDE + c * 16;
            cp_async16(dst, src);
        }
    };

    auto addrA = [&](uint32_t tbase, int mt, int ks) -> uint32_t {
        int row = wm * 64 + mt * 16 + (lane & 15);
        int kh  = (lane >> 4) & 1;
        return tbase + row * GT_STRIDE + ks * 32 + kh * 16;
    };
    auto addrB = [&](uint32_t tbase, int np, int ks) -> uint32_t {
        int row = wn * 32 + np * 16 + (lane & 7) + (((lane >> 4) & 1) << 3);
        int kh  = (lane >> 3) & 1;
        return tbase + row * GT_STRIDE + ks * 32 + kh * 16;
    };

    load_chunk(0, 0);
    CP_COMMIT();

    const int NCHUNK = E_ / 32;
#pragma unroll 1
    for (int ch = 0; ch < NCHUNK; ch++) {
        const int buf = ch & 1;
        if (ch + 1 < NCHUNK) {
            load_chunk(ch + 1, buf ^ 1);
            CP_COMMIT();
            CP_WAIT(1);
        } else {
            CP_WAIT(0);
        }
        __syncthreads();

        const uint32_t tAhi = sb + buf * GBUF_BYTES;
        const uint32_t tAlo = tAhi + GT_BYTES;
        const uint32_t tWhi = tAhi + 2 * GT_BYTES;
        const uint32_t tWlo = tAhi + 3 * GT_BYTES;

#pragma unroll
        for (int ks = 0; ks < 2; ks++) {
            uint32_t ahi[4][4], alo[4][4], bhi[2][4], blo[2][4];
#pragma unroll
            for (int mt = 0; mt < 4; mt++) ldsm4(ahi[mt], addrA(tAhi, mt, ks));
#pragma unroll
            for (int mt = 0; mt < 4; mt++) ldsm4(alo[mt], addrA(tAlo, mt, ks));
#pragma unroll
            for (int np = 0; np < 2; np++) ldsm4(bhi[np], addrB(tWhi, np, ks));
#pragma unroll
            for (int np = 0; np < 2; np++) ldsm4(blo[np], addrB(tWlo, np, ks));
#pragma unroll
            for (int mt = 0; mt < 4; mt++)
#pragma unroll
                for (int nt = 0; nt < 4; nt++) {
                    const int np = nt >> 1, hf = (nt & 1) * 2;
                    mma16816(acc[mt][nt], ahi[mt], &bhi[np][hf]);
                    mma16816(acc[mt][nt], ahi[mt], &blo[np][hf]);
                    mma16816(acc[mt][nt], alo[mt], &bhi[np][hf]);
                }
        }
        __syncthreads();
    }

    const int quad = lane >> 2, qd = (lane & 3) * 2;
#pragma unroll
    for (int mt = 0; mt < 4; mt++) {
#pragma unroll
        for (int nt = 0; nt < 4; nt++) {
            int row0 = m0 + wm * 64 + mt * 16 + quad;
            int col  = n0 + wn * 32 + nt * 8 + qd;
            float b0 = bias[col], b1 = bias[col + 1];
            float2 v0 = make_float2(acc[mt][nt][0] + b0, acc[mt][nt][1] + b1);
            float2 v1 = make_float2(acc[mt][nt][2] + b0, acc[mt][nt][3] + b1);
            *(float2*)(C + (size_t)row0 * E_ + col) = v0;
            *(float2*)(C + (size_t)(row0 + 8) * E_ + col) = v1;
        }
    }
}

// ---------------------------------------------------------------------------
// Fused RMSNorm + RoPE + transpose -> bf16 hi/lo [B*H][T][D]
// q pre-scaled by 1/sqrt(D) = 0.125
// ---------------------------------------------------------------------------
__global__ __launch_bounds__(256) void normrope_kernel(
    const float* __restrict__ ql, const float* __restrict__ kl,
    const float* __restrict__ vl,
    const float* __restrict__ cosp, const float* __restrict__ sinp,
    __nv_bfloat16* __restrict__ qhi, __nv_bfloat16* __restrict__ qlo,
    __nv_bfloat16* __restrict__ khi, __nv_bfloat16* __restrict__ klo,
    __nv_bfloat16* __restrict__ vhi, __nv_bfloat16* __restrict__ vlo)
{
    int w    = blockIdx.x * 8 + (threadIdx.x >> 5);
    int lane = threadIdx.x & 31;
    int h = w & 15;
    int t = (w >> 4) & 2047;
    int b = w >> 15;

    size_t in_base  = ((size_t)(b * T_ + t)) * E_ + h * D_;
    size_t out_base = ((size_t)((b * H_ + h) * T_ + t)) * D_;

    float c = cosp[t * 32 + lane];
    float s = sinp[t * 32 + lane];

    {
        float x1 = ql[in_base + lane];
        float x2 = ql[in_base + lane + 32];
        float ss = x1 * x1 + x2 * x2;
#pragma unroll
        for (int o = 16; o > 0; o >>= 1) ss += __shfl_xor_sync(0xffffffffu, ss, o);
        float r = rsqrtf(ss * (1.0f / 64.0f) + 1e-6f) * 0.125f;   // fold 1/sqrt(D)
        float y1 = (x1 * c - x2 * s) * r;
        float y2 = (x2 * c + x1 * s) * r;
        __nv_bfloat16 h1 = __float2bfloat16(y1), h2 = __float2bfloat16(y2);
        qhi[out_base + lane]      = h1;
        qhi[out_base + lane + 32] = h2;
        qlo[out_base + lane]      = __float2bfloat16(y1 - __bfloat162float(h1));
        qlo[out_base + lane + 32] = __float2bfloat16(y2 - __bfloat162float(h2));
    }
    {
        float x1 = kl[in_base + lane];
        float x2 = kl[in_base + lane + 32];
        float ss = x1 * x1 + x2 * x2;
#pragma unroll
        for (int o = 16; o > 0; o >>= 1) ss += __shfl_xor_sync(0xffffffffu, ss, o);
        float r = rsqrtf(ss * (1.0f / 64.0f) + 1e-6f);
        float y1 = (x1 * c - x2 * s) * r;
        float y2 = (x2 * c + x1 * s) * r;
        __nv_bfloat16 h1 = __float2bfloat16(y1), h2 = __float2bfloat16(y2);
        khi[out_base + lane]      = h1;
        khi[out_base + lane + 32] = h2;
        klo[out_base + lane]      = __float2bfloat16(y1 - __bfloat162float(h1));
        klo[out_base + lane + 32] = __float2bfloat16(y2 - __bfloat162float(h2));
    }
    {
        float y1 = vl[in_base + lane];
        float y2 = vl[in_base + lane + 32];
        __nv_bfloat16 h1 = __float2bfloat16(y1), h2 = __float2bfloat16(y2);
        vhi[out_base + lane]      = h1;
        vhi[out_base + lane + 32] = h2;
        vlo[out_base + lane]      = __float2bfloat16(y1 - __bfloat162float(h1));
        vlo[out_base + lane + 32] = __float2bfloat16(y2 - __bfloat162float(h2));
    }
}

// ---------------------------------------------------------------------------
// Flash attention on mma.sync (bf16 hi/lo splits), causal.
// CTA = 64 q rows (4 warps x m16). K-tile 64. Output written pre-split into
// Ohi/Olo in [B,T,E] layout for the final projection.
// ---------------------------------------------------------------------------
#define FT_STRIDE 144
#define FT_TILE   (64 * FT_STRIDE)       // 9216
#define FKV_BUF   (4 * FT_TILE)          // 36864
#define FSMEM     (2 * FKV_BUF + 2 * FT_TILE)   // 92160

__global__ __launch_bounds__(128) void flash_mma(
    const __nv_bfloat16* __restrict__ qhi, const __nv_bfloat16* __restrict__ qlo,
    const __nv_bfloat16* __restrict__ khi, const __nv_bfloat16* __restrict__ klo,
    const __nv_bfloat16* __restrict__ vhi, const __nv_bfloat16* __restrict__ vlo,
    __nv_bfloat16* __restrict__ Ohi, __nv_bfloat16* __restrict__ Olo)
{
    extern __shared__ char smem[];
    const int tid = threadIdx.x, lane = tid & 31, w = tid >> 5;
    const int bh = blockIdx.y;
    const int qt = (int)gridDim.x - 1 - (int)blockIdx.x;  // heavy tiles first
    const uint32_t sb = smem_u32(smem);
    const uint32_t sQ = sb + 2 * FKV_BUF;

    const size_t bhbase = (size_t)bh * T_ * D_;

    auto load_kv = [&](int kt, int buf) {
        const char* srcs[4] = {
            (const char*)(khi + bhbase + (size_t)kt * 64 * D_),
            (const char*)(klo + bhbase + (size_t)kt * 64 * D_),
            (const char*)(vhi + bhbase + (size_t)kt * 64 * D_),
            (const char*)(vlo + bhbase + (size_t)kt * 64 * D_) };
#pragma unroll
        for (int i = 0; i < 16; i++) {
            int idx = i * 128 + tid;
            int tile = idx >> 9, rem = idx & 511, r = rem >> 3, c = rem & 7;
            cp_async16(sb + buf * FKV_BUF + tile * FT_TILE + r * FT_STRIDE + c * 16,
                       srcs[tile] + r * 128 + c * 16);
        }
    };

    load_kv(0, 0);
    CP_COMMIT();

    // Q tiles (hi/lo) into smem
    {
        const char* qh8 = (const char*)(qhi + bhbase + (size_t)qt * 64 * D_);
        const char* ql8 = (const char*)(qlo + bhbase + (size_t)qt * 64 * D_);
#pragma unroll
        for (int i = 0; i < 4; i++) {
            int idx = i * 128 + tid;
            int r = idx >> 3, c = idx & 7;
            *(uint4*)(smem + 2 * FKV_BUF + r * FT_STRIDE + c * 16) =
                *(const uint4*)(qh8 + r * 128 + c * 16);
            *(uint4*)(smem + 2 * FKV_BUF + FT_TILE + r * FT_STRIDE + c * 16) =
                *(const uint4*)(ql8 + r * 128 + c * 16);
        }
    }
    __syncthreads();

    // Q A-fragments (persistent)
    uint32_t qa_h[4][4], qa_l[4][4];
    {
        int row = w * 16 + (lane & 15);
        int kh = (lane >> 4) & 1;
#pragma unroll
        for (int ks = 0; ks < 4; ks++) {
            ldsm4(qa_h[ks], sQ + row * FT_STRIDE + ks * 32 + kh * 16);
            ldsm4(qa_l[ks], sQ + FT_TILE + row * FT_STRIDE + ks * 32 + kh * 16);
        }
    }

    float o[8][4];
#pragma unroll
    for (int i = 0; i < 8; i++)
#pragma unroll
        for (int j = 0; j < 4; j++) o[i][j] = 0.f;
    float m0 = -INFINITY, m1 = -INFINITY, l0 = 0.f, l1 = 0.f;

#pragma unroll 1
    for (int kt = 0; kt <= qt; kt++) {
        const int buf = kt & 1;
        if (kt < qt) { load_kv(kt + 1, buf ^ 1); CP_COMMIT(); CP_WAIT(1); }
        else         { CP_WAIT(0); }
        __syncthreads();

        const uint32_t tKh = sb + buf * FKV_BUF;
        const uint32_t tKl = tKh + FT_TILE;
        const uint32_t tVh = tKh + 2 * FT_TILE;
        const uint32_t tVl = tKh + 3 * FT_TILE;

        // ---- S = Q @ K^T (3-term split) ----
        float s[8][4];
#pragma unroll
        for (int i = 0; i < 8; i++)
#pragma unroll
            for (int j = 0; j < 4; j++) s[i][j] = 0.f;
        {
            const int rowB = (lane & 7) + (((lane >> 4) & 1) << 3);
            const int khB  = (lane >> 3) & 1;
#pragma unroll
            for (int ks = 0; ks < 4; ks++) {
                uint32_t bh_[4][4], bl_[4][4];
#pragma unroll
                for (int np = 0; np < 4; np++) {
                    uint32_t off = (np * 16 + rowB) * FT_STRIDE + ks * 32 + khB * 16;
                    ldsm4(bh_[np], tKh + off);
                    ldsm4(bl_[np], tKl + off);
                }
#pragma unroll
                for (int nt = 0; nt < 8; nt++) {
                    const int np = nt >> 1, hf = (nt & 1) * 2;
                    mma16816(s[nt], qa_h[ks], &bh_[np][hf]);
                    mma16816(s[nt], qa_h[ks], &bl_[np][hf]);
                    mma16816(s[nt], qa_l[ks], &bh_[np][hf]);
                }
            }
        }

        // ---- causal mask on diagonal tile ----
        if (kt == qt) {
            const int r0 = qt * 64 + w * 16 + (lane >> 2);
            const int cb = kt * 64 + (lane & 3) * 2;
#pragma unroll
            for (int nt = 0; nt < 8; nt++) {
                int j0 = cb + nt * 8, j1 = j0 + 1;
                if (j0 > r0)     s[nt][0] = -INFINITY;
                if (j1 > r0)     s[nt][1] = -INFINITY;
                if (j0 > r0 + 8) s[nt][2] = -INFINITY;
                if (j1 > r0 + 8) s[nt][3] = -INFINITY;
            }
        }

        // ---- online softmax ----
        float tm0 = -INFINITY, tm1 = -INFINITY;
#pragma unroll
        for (int nt = 0; nt < 8; nt++) {
            tm0 = fmaxf(tm0, fmaxf(s[nt][0], s[nt][1]));
            tm1 = fmaxf(tm1, fmaxf(s[nt][2], s[nt][3]));
        }
        tm0 = fmaxf(tm0, __shfl_xor_sync(0xffffffffu, tm0, 1));
        tm0 = fmaxf(tm0, __shfl_xor_sync(0xffffffffu, tm0, 2));
        tm1 = fmaxf(tm1, __shfl_xor_sync(0xffffffffu, tm1, 1));
        tm1 = fmaxf(tm1, __shfl_xor_sync(0xffffffffu, tm1, 2));
        float mn0 = fmaxf(m0, tm0), mn1 = fmaxf(m1, tm1);
        float f0 = __expf(m0 - mn0), f1 = __expf(m1 - mn1);
        m0 = mn0; m1 = mn1;
        float rs0 = 0.f, rs1 = 0.f;
#pragma unroll
        for (int nt = 0; nt < 8; nt++) {
            s[nt][0] = __expf(s[nt][0] - mn0);
            s[nt][1] = __expf(s[nt][1] - mn0);
            s[nt][2] = __expf(s[nt][2] - mn1);
            s[nt][3] = __expf(s[nt][3] - mn1);
            rs0 += s[nt][0] + s[nt][1];
            rs1 += s[nt][2] + s[nt][3];
        }
        l0 = l0 * f0 + rs0;
        l1 = l1 * f1 + rs1;
#pragma unroll
        for (int dt = 0; dt < 8; dt++) {
            o[dt][0] *= f0; o[dt][1] *= f0;
            o[dt][2] *= f1; o[dt][3] *= f1;
        }

        // ---- O += P @ V (3-term split), P fragments from S regs ----
        {
            const int rowV = (lane & 15);
            const int colV = ((lane >> 4) & 1) * 16;
#pragma unroll
            for (int js = 0; js < 4; js++) {
                uint32_t pa_h[4], pa_l[4];
                split_pack(s[2 * js][0],     s[2 * js][1],     pa_h[0], pa_l[0]);
                split_pack(s[2 * js][2],     s[2 * js][3],     pa_h[1], pa_l[1]);
                split_pack(s[2 * js + 1][0], s[2 * js + 1][1], pa_h[2], pa_l[2]);
                split_pack(s[2 * js + 1][2], s[2 * js + 1][3], pa_h[3], pa_l[3]);

                uint32_t bvh[4][4], bvl[4][4];
#pragma unroll
                for (int ng = 0; ng < 4; ng++) {
                    uint32_t off = (js * 16 + rowV) * FT_STRIDE + ng * 32 + colV;
                    ldsm4t(bvh[ng], tVh + off);
                    ldsm4t(bvl[ng], tVl + off);
                }
#pragma unroll
                for (int dt = 0; dt < 8; dt++) {
                    const int np = dt >> 1, hf = (dt & 1) * 2;
                    mma16816(o[dt], pa_h, &bvh[np][hf]);
                    mma16816(o[dt], pa_h, &bvl[np][hf]);
                    mma16816(o[dt], pa_l, &bvh[np][hf]);
                }
            }
        }
        __syncthreads();
    }

    // ---- epilogue: normalize, split into bf16 hi/lo, store [B,T,E] ----
    l0 += __shfl_xor_sync(0xffffffffu, l0, 1);
    l0 += __shfl_xor_sync(0xffffffffu, l0, 2);
    l1 += __shfl_xor_sync(0xffffffffu, l1, 1);
    l1 += __shfl_xor_sync(0xffffffffu, l1, 2);
    const float inv0 = 1.0f / l0, inv1 = 1.0f / l1;

    const int b = bh >> 4, h = bh & 15;
    const int r0 = qt * 64 + w * 16 + (lane >> 2);
    const int cb = h * 64 + (lane & 3) * 2;
#pragma unroll
    for (int dt = 0; dt < 8; dt++) {
        size_t a0 = ((size_t)(b * T_ + r0)) * E_ + cb + dt * 8;
        size_t a1 = ((size_t)(b * T_ + r0 + 8)) * E_ + cb + dt * 8;
        float v00 = o[dt][0] * inv0, v01 = o[dt][1] * inv0;
        float v10 = o[dt][2] * inv1, v11 = o[dt][3] * inv1;
        uint32_t h0, l0r, h1, l1r;
        split_pack(v00, v01, h0, l0r);
        split_pack(v10, v11, h1, l1r);
        *(uint32_t*)(Ohi + a0) = h0;
        *(uint32_t*)(Olo + a0) = l0r;
        *(uint32_t*)(Ohi + a1) = h1;
        *(uint32_t*)(Olo + a1) = l1r;
    }
}

// ---------------------------------------------------------------------------
// Launch
// ---------------------------------------------------------------------------
extern "C" void kernel_launch(void* const* d_in, const int* in_sizes, int n_in,
                              void* d_out, int out_size)
{
    const float* query = (const float*)d_in[0];
    const float* key   = (const float*)d_in[1];
    const float* value = (const float*)d_in[2];
    const float* cosp  = (const float*)d_in[4];
    const float* sinp  = (const float*)d_in[5];
    const float* Wq = (const float*)d_in[6];
    const float* bq = (const float*)d_in[7];
    const float* Wk = (const float*)d_in[8];
    const float* bk = (const float*)d_in[9];
    const float* Wv = (const float*)d_in[10];
    const float* bv = (const float*)d_in[11];
    const float* Wo = (const float*)d_in[12];
    const float* bo = (const float*)d_in[13];
    float* out = (float*)d_out;

    float *qlin, *klin, *vlin;
    __nv_bfloat16 *ahi, *alo, *whi, *wlo;
    __nv_bfloat16 *qhi, *qlo, *khi, *klo, *vhi, *vlo;
    cudaGetSymbolAddress((void**)&qlin, g_qlin);
    cudaGetSymbolAddress((void**)&klin, g_klin);
    cudaGetSymbolAddress((void**)&vlin, g_vlin);
    cudaGetSymbolAddress((void**)&ahi,  g_ahi);
    cudaGetSymbolAddress((void**)&alo,  g_alo);
    cudaGetSymbolAddress((void**)&whi,  g_whi);
    cudaGetSymbolAddress((void**)&wlo,  g_wlo);
    cudaGetSymbolAddress((void**)&qhi,  g_qhi);
    cudaGetSymbolAddress((void**)&qlo,  g_qlo);
    cudaGetSymbolAddress((void**)&khi,  g_khi);
    cudaGetSymbolAddress((void**)&klo,  g_klo);
    cudaGetSymbolAddress((void**)&vhi,  g_vhi);
    cudaGetSymbolAddress((void**)&vlo,  g_vlo);

    cudaFuncSetAttribute(gemm_mma, cudaFuncAttributeMaxDynamicSharedMemorySize,
                         GSMEM_TOTAL);
    cudaFuncSetAttribute(flash_mma, cudaFuncAttributeMaxDynamicSharedMemorySize,
                         FSMEM);

    const int nA = M_ * E_, nW = E_ * E_;
    dim3 ggrid(E_ / 128, M_ / 128);   // (8, 64)

    // Q projection
    cvt_split<<<nA / 1024, 256>>>(query, ahi, alo, nA);
    cvt_split<<<nW / 1024, 256>>>(Wq, whi, wlo, nW);
    gemm_mma<<<ggrid, 256, GSMEM_TOTAL>>>(ahi, alo, whi, wlo, bq, qlin);
    // K projection
    cvt_split<<<nA / 1024, 256>>>(key, ahi, alo, nA);
    cvt_split<<<nW / 1024, 256>>>(Wk, whi, wlo, nW);
    gemm_mma<<<ggrid, 256, GSMEM_TOTAL>>>(ahi, alo, whi, wlo, bk, klin);
    // V projection
    cvt_split<<<nA / 1024, 256>>>(value, ahi, alo, nA);
    cvt_split<<<nW / 1024, 256>>>(Wv, whi, wlo, nW);
    gemm_mma<<<ggrid, 256, GSMEM_TOTAL>>>(ahi, alo, whi, wlo, bv, vlin);

    // RMSNorm + RoPE + transpose + bf16 hi/lo split
    normrope_kernel<<<(B_ * T_ * H_) / 8, 256>>>(qlin, klin, vlin, cosp, sinp,
                                                 qhi, qlo, khi, klo, vhi, vlo);

    // Flash attention (writes output pre-split into ahi/alo, [B,T,E])
    flash_mma<<<dim3(T_ / 64, B_ * H_), 128, FSMEM>>>(qhi, qlo, khi, klo,
                                                      vhi, vlo, ahi, alo);

    // Output projection
    cvt_split<<<nW / 1024, 256>>>(Wo, whi, wlo, nW);
    gemm_mma<<<ggrid, 256, GSMEM_TOTAL>>>(ahi, alo, whi, wlo, bo, out);
}